// round 13
// baseline (speedup 1.0000x reference)
#include <cuda_runtime.h>

// QuantumRegression: 1024 x 14-qubit statevector sim, 3 layers (Rot per wire + CNOT ring),
// <Z_w> features, linear head.
//
// R13: R12 (3-pass 5+5+4 structure at NT=1024, A/B tiles split across thread pairs with
// the 5th wire's RY done via shfl_xor 16) with the passA (L>=1) deferred-beta table index
// FIXED: idx = (h<<6)|(F<<1)|t0 with h = t>>5, F = (f4<<1)|s, t0 = t&1
//        -> tab + ((t>>5)<<6) + ((s<<1)|(t&1)), step f4<<2.
// ZYZ deferred-beta tables, frame-tracked CNOT perms, XOR-staggered pass C and Walsh
// measurement identical to R10 (proven correct at 220.7us).

#define NW   14
#define DIM  16384
#define NT   1024

typedef unsigned long long u64;

// table offsets (float4 {c,c,-s,s}) — identical contents to R10
#define OFF_A0  0        // 32    : layer0 entry A (deltas only), idx F
#define OFF_A1  32       // 2048  : layer1 entry A, idx (h<<6)|(F<<1)|t0
#define OFF_A2  2080     // 2048  : layer2 entry A
#define OFF_B0  4128     // 32    : layer0 entry B, idx F
#define OFF_B1  4160     // 512   : layer1 entry B, idx (F<<4)|q
#define OFF_B2  4672     // 512   : layer2 entry B
#define OFF_C   5184     // 3x16  : entry C per layer, idx m^u
#define NTAB    5232

__device__ float2 g_rot[3*NW];          // per-wire (cos g/2, sin g/2)
__device__ float4 g_tab[NTAB];

// ---------------- setup: ZYZ decomposition + deferred-diagonal tables ----------------

struct cpx { float re, im; };
__device__ __forceinline__ cpx cmul(cpx a, cpx b){
    cpx r; r.re = a.re*b.re - a.im*b.im; r.im = a.re*b.im + a.im*b.re; return r;
}

__device__ void rotmat(const float* p, cpx U[2][2]){
    float cx = cosf(0.5f*p[0]), sx = sinf(0.5f*p[0]);
    float cy = cosf(0.5f*p[1]), sy = sinf(0.5f*p[1]);
    float cz = cosf(0.5f*p[2]), sz = sinf(0.5f*p[2]);
    cpx r00 = { cy*cx,  sy*sx};
    cpx r01 = {-sy*cx, -cy*sx};
    cpx r10 = { sy*cx, -cy*sx};
    cpx r11 = { cy*cx, -sy*sx};
    cpx e0 = {cz, -sz}, e1 = {cz, sz};
    U[0][0] = cmul(e0, r00); U[0][1] = cmul(e0, r01);
    U[1][0] = cmul(e1, r10); U[1][1] = cmul(e1, r11);
}

__device__ __forceinline__ float angsum(const float* a, int w0, int bits, int nb){
    float s = 0.f;
    for (int k = 0; k < nb; k++){
        float h = 0.5f * a[w0 - k];
        s += ((bits >> k) & 1) ? h : -h;
    }
    return s;
}

__global__ void setup_all(const float* __restrict__ vp){
    __shared__ float sb[3*NW], sd[3*NW];
    int t = threadIdx.x;
    if (t < 3*NW){
        cpx U[2][2]; rotmat(vp + t*3, U);
        float na = hypotf(U[0][0].re, U[0][0].im);
        float nc = hypotf(U[1][0].re, U[1][0].im);
        float n  = hypotf(na, nc);
        g_rot[t] = make_float2(na/n, nc/n);
        float beta, delta;
        if (nc > 1e-6f && na > 1e-6f){
            float aa = atan2f(U[0][0].im, U[0][0].re);
            float ac = atan2f(U[1][0].im, U[1][0].re);
            float ad = atan2f(U[1][1].im, U[1][1].re);
            beta = ac - aa; delta = ad - ac;
        } else if (nc <= 1e-6f){
            delta = 0.f;
            beta = atan2f(U[1][1].im, U[1][1].re) - atan2f(U[0][0].im, U[0][0].re);
        } else {
            delta = 0.f;
            beta = atan2f(U[1][0].im, U[1][0].re) - atan2f(-U[0][1].im, -U[0][1].re);
        }
        sb[t] = beta; sd[t] = delta;
    }
    __syncthreads();
    for (int idx = t; idx < NTAB; idx += blockDim.x){
        float ang;
        if (idx < OFF_A1){
            ang = angsum(sd, 0*NW + 4, idx, 5);
        } else if (idx < OFF_B0){
            int l = (idx < OFF_A2) ? 1 : 2;
            int r = idx - ((l == 1) ? OFF_A1 : OFF_A2);
            int h = r >> 6, f = (r >> 1) & 31, t0 = r & 1;
            int sA = (f ^ (f >> 1)) ^ (t0 ? 0x18 : 0);
            int sB = (h ^ (h >> 1)) ^ ((f & 1) ? 0x10 : 0);
            ang = angsum(sd, l*NW + 4, f, 5)
                + angsum(sb, (l-1)*NW + 4, sA, 5)
                + angsum(sb, (l-1)*NW + 9, sB, 5);
        } else if (idx < OFF_B1){
            ang = angsum(sd, 0*NW + 9, idx - OFF_B0, 5);
        } else if (idx < OFF_C){
            int l = (idx < OFF_B2) ? 1 : 2;
            int r = idx - ((l == 1) ? OFF_B1 : OFF_B2);
            int f = r >> 4, q = r & 15;
            int sC = (q ^ (q >> 1)) ^ ((f & 1) ? 8 : 0);
            ang = angsum(sd, l*NW + 9, f, 5)
                + angsum(sb, (l-1)*NW + 13, sC, 4);
        } else {
            int r = idx - OFF_C; int l = r >> 4, m = r & 15;
            ang = angsum(sd, l*NW + 13, m, 4);
        }
        float sp, cp; sincosf(ang, &sp, &cp);
        g_tab[idx] = make_float4(cp, cp, -sp, sp);
    }
}

// ---------------- packed f32x2 helpers ----------------

__device__ __forceinline__ u64 pk2(float lo, float hi){
    u64 r; asm("mov.b64 %0, {%1,%2};" : "=l"(r) : "f"(lo), "f"(hi)); return r;
}
__device__ __forceinline__ void upk2(u64 v, float& lo, float& hi){
    asm("mov.b64 {%0,%1}, %2;" : "=f"(lo), "=f"(hi) : "l"(v));
}
__device__ __forceinline__ u64 swp2(u64 v){
    u64 r;
    asm("{ .reg .b32 a,b; mov.b64 {a,b}, %1; mov.b64 %0, {b,a}; }" : "=l"(r) : "l"(v));
    return r;
}
__device__ __forceinline__ u64 f2(u64 a, u64 b, u64 c){
    u64 r; asm("fma.rn.f32x2 %0, %1, %2, %3;" : "=l"(r) : "l"(a), "l"(b), "l"(c)); return r;
}
__device__ __forceinline__ u64 m2(u64 a, u64 b){
    u64 r; asm("mul.rn.f32x2 %0, %1, %2;" : "=l"(r) : "l"(a), "l"(b)); return r;
}
__device__ __forceinline__ u64 dmul(u64 amp, float4 q){
    u64 uu = pk2(q.x, q.y), nn = pk2(q.z, q.w);
    return f2(uu, amp, m2(nn, swp2(amp)));
}
__device__ __forceinline__ u64 shflx16(u64 v){
    return __shfl_xor_sync(0xffffffffu, v, 16);
}

// NB real RY rotations on bits NB-1..0 of a 2^NB-amp tile; bit k <-> wire w0-k.
template<int NB>
__device__ __forceinline__ void rotTile(u64* amp, const float2* rot, int w0, int u){
    #pragma unroll
    for (int k = NB-1; k >= 0; k--){
        float2 cs = rot[w0 - k];
        float s = ((u >> k) & 1) ? -cs.y : cs.y;
        u64 cc = pk2(cs.x, cs.x), ss = pk2(s, s), ns = pk2(-s, -s);
        const int bit = 1 << k;
        #pragma unroll
        for (int p = 0; p < (1 << NB); p++)
            if (!(p & bit)){
                u64 v0 = amp[p], v1 = amp[p | bit];
                amp[p]       = f2(cc, v0, m2(ns, v1));
                amp[p | bit] = f2(cc, v1, m2(ss, v0));
            }
    }
}

// shfl rotation on the pair bit (s = this thread's side), wire `wire`
__device__ __forceinline__ void rotShfl16(u64* amp, const float2* rot, int wire, int s){
    float2 cs = rot[wire];
    u64 cc = pk2(cs.x, cs.x);
    float sg = s ? cs.y : -cs.y;
    u64 sgn = pk2(sg, sg);
    #pragma unroll
    for (int f = 0; f < 16; f++){
        u64 o = shflx16(amp[f]);
        amp[f] = f2(cc, amp[f], m2(sgn, o));
    }
}

// ---------------- CNOT-ring permutation (GF2 linear, constexpr-foldable) ----------------
__host__ __device__ __forceinline__ constexpr int cpfwd(int i){
    int y = i;
    y ^= y >> 1; y ^= y >> 2; y ^= y >> 4; y ^= y >> 8;
    return (y & 0x1FFF) ^ ((((y ^ (i >> 13)) & 1) << 13));
}
__host__ __device__ __forceinline__ constexpr int cpinv(int o){
    int t = o ^ (o >> 1);
    return (t & 0x1FFF) ^ (o & 0x2000) ^ ((o & 1) ? 0x3000 : 0);
}
template<int L>
__host__ __device__ __forceinline__ constexpr int pinvL(int x){
    return (L == 0) ? x : (L == 1) ? cpinv(x) : cpinv(cpinv(x));
}

// ---------------- passes ----------------
// pass A thread decomposition: s = (t>>4)&1, tau = ((t>>5)<<4)|(t&15) (9 bits)
//   half-tile: 16 amps x = (f4<<10)|(s<<9)|tau; wires 0..3 in regs, wire 4 (bit 9) via shfl.

template<int L>
__device__ __forceinline__ void passA(float2* psi, const float4* stab, const float2* srot, int t){
    const int s = (t >> 4) & 1;
    const int tau = ((t >> 5) << 4) | (t & 15);
    const int xbase = (s << 9) | tau;
    const int base = pinvL<L>(xbase);
    // idx = (h<<6)|(F<<1)|t0, h = t>>5 (x bits 8..4), F = (f4<<1)|s, t0 = t&1
    const float4* tab = stab + ((L == 1) ? OFF_A1 : OFF_A2)
                       + ((t >> 5) << 6) + ((s << 1) | (t & 1));
    u64 amp[16];
    #pragma unroll
    for (int f = 0; f < 16; f++){
        float2 a = psi[base ^ pinvL<L>(f << 10)];
        amp[f] = dmul(pk2(a.x, a.y), tab[f << 2]);
    }
    rotTile<4>(amp, srot, L*NW + 3, 0);       // wires 0..3 (bits 13..10)
    rotShfl16(amp, srot, L*NW + 4, s);        // wire 4 (bit 9)
    #pragma unroll
    for (int f = 0; f < 16; f++){
        float xx, yy; upk2(amp[f], xx, yy);
        psi[base ^ pinvL<L>(f << 10)] = make_float2(xx, yy);
    }
}

// pass B: q = t&15, s = (t>>4)&1, g5 = t>>5; amps x = (g5<<9)|(f4<<5)|(s<<4)|q
template<int L>
__device__ __forceinline__ void passB(float2* psi, const float4* stab, const float2* srot, int t){
    const int q = t & 15;
    const int s = (t >> 4) & 1;
    const int g5 = t >> 5;
    const int xbase = (g5 << 9) | (s << 4) | q;
    const int base = pinvL<L>(xbase);
    u64 amp[16];
    if (L == 0){
        const float4* tab = stab + OFF_B0 + s;          // idx F = (f4<<1)|s
        #pragma unroll
        for (int f = 0; f < 16; f++){
            float2 a = psi[base ^ pinvL<L>(f << 5)];
            amp[f] = dmul(pk2(a.x, a.y), tab[f << 1]);
        }
    } else {
        const float4* tab = stab + ((L == 1) ? OFF_B1 : OFF_B2) + (s << 4) + q;  // idx (F<<4)|q
        #pragma unroll
        for (int f = 0; f < 16; f++){
            float2 a = psi[base ^ pinvL<L>(f << 5)];
            amp[f] = dmul(pk2(a.x, a.y), tab[f << 5]);
        }
    }
    rotTile<4>(amp, srot, L*NW + 8, 0);       // wires 5..8 (bits 8..5)
    rotShfl16(amp, srot, L*NW + 9, s);        // wire 9 (bit 4)
    #pragma unroll
    for (int f = 0; f < 16; f++){
        float xx, yy; upk2(amp[f], xx, yy);
        psi[base ^ pinvL<L>(f << 5)] = make_float2(xx, yy);
    }
}

// stagger offset u for C passes (same derivation as R10; depends only on low bits of t)
template<int L>
__device__ __forceinline__ int p3stagger(int t){
    int r4 = t & 15;
    if (L == 0) return r4;
    if (L == 1){ int v = r4 ^ ((t & 1) << 3); return (v ^ (v>>1) ^ (v>>2) ^ (v>>3)) & 15; }
    int v = r4 ^ ((t & 3) << 2); return (v ^ (v >> 2)) & 15;
}

// pass C: logical bits 3..0 (wires 10..13), layer L; ONE 16-amp tile per thread (y = t).
template<int L, bool MEAS>
__device__ __forceinline__ void passC(float2* psi, const float4* stab, const float2* srot,
                                      int t, float* zs){
    const float4* tabC = stab + OFF_C + L*16;
    const int u = p3stagger<L>(t);
    const int y = t;                             // 10-bit tile index
    const int base = pinvL<L>(y << 4) ^ pinvL<L>(u);
    u64 amp[16];
    #pragma unroll
    for (int m = 0; m < 16; m++){
        float2 a = psi[base ^ pinvL<L>(m)];
        amp[m] = dmul(pk2(a.x, a.y), tabC[m ^ u]);
    }
    rotTile<4>(amp, srot, L*NW + 13, u);
    if (!MEAS){
        #pragma unroll
        for (int m = 0; m < 16; m++){
            float xx, yy; upk2(amp[m], xx, yy);
            psi[base ^ pinvL<L>(m)] = make_float2(xx, yy);
        }
    } else {
        int obase = cpfwd((y << 4) ^ u);
        float pr[16];
        #pragma unroll
        for (int m = 0; m < 16; m++){
            float xx, yy; upk2(amp[m], xx, yy);
            pr[m] = xx*xx + yy*yy;
        }
        float P[8], Mv[8];
        #pragma unroll
        for (int j = 0; j < 8; j++){ P[j] = pr[2*j] + pr[2*j+1]; Mv[j] = pr[2*j] - pr[2*j+1]; }
        float Spar = Mv[0]-Mv[1]-Mv[2]+Mv[3]-Mv[4]+Mv[5]+Mv[6]-Mv[7];
        float PP[4], PM[4];
        #pragma unroll
        for (int k = 0; k < 4; k++){ PP[k] = P[2*k] + P[2*k+1]; PM[k] = P[2*k] - P[2*k+1]; }
        float S123 = PM[0]-PM[1]-PM[2]+PM[3];
        float PPP0 = PP[0]+PP[1], PPP1 = PP[2]+PP[3];
        float S23  = (PP[0]-PP[1]) - (PP[2]-PP[3]);
        float T    = PPP0 + PPP1;
        float S3   = PPP0 - PPP1;
        #pragma unroll
        for (int w = 1; w <= 9; w++){
            unsigned msk = ((unsigned)obase << (18 + w)) & 0x80000000u;
            zs[w] += __uint_as_float(__float_as_uint(T) ^ msk);
        }
        zs[0]  += __uint_as_float(__float_as_uint(Spar) ^ (((unsigned)obase << 18) & 0x80000000u));
        zs[13] += __uint_as_float(__float_as_uint(Spar) ^ (((unsigned)obase << 31) & 0x80000000u));
        zs[12] += __uint_as_float(__float_as_uint(S123) ^ (((unsigned)obase << 30) & 0x80000000u));
        zs[11] += __uint_as_float(__float_as_uint(S23)  ^ (((unsigned)obase << 29) & 0x80000000u));
        zs[10] += __uint_as_float(__float_as_uint(S3)   ^ (((unsigned)obase << 28) & 0x80000000u));
    }
}

// ---------------- main kernel ----------------

__global__ void __launch_bounds__(NT, 1)
qsim_kernel(const float* __restrict__ sr, const float* __restrict__ si,
            const float* __restrict__ hw, const float* __restrict__ hb,
            float* __restrict__ out)
{
    extern __shared__ float2 sm[];
    float2* psi = sm;
    float4* stab = reinterpret_cast<float4*>(sm + DIM);
    float2* srot = reinterpret_cast<float2*>(stab + NTAB);
    const int t = threadIdx.x;
    const int b = blockIdx.x;

    #pragma unroll 1
    for (int i = t; i < NTAB; i += NT) stab[i] = g_tab[i];
    if (t < 3*NW) srot[t] = g_rot[t];
    __syncthreads();

    // ---- layer 0 pass A fused with global load ----
    {
        const float* srb = sr + (size_t)b * DIM;
        const float* sib = si + (size_t)b * DIM;
        const int s = (t >> 4) & 1;
        const int tau = ((t >> 5) << 4) | (t & 15);
        const int xbase = (s << 9) | tau;
        const float4* tab = stab + OFF_A0 + s;     // idx F = (f4<<1)|s
        u64 amp[16];
        #pragma unroll
        for (int f = 0; f < 16; f++){
            int x = (f << 10) | xbase;
            float re = __ldg(srb + x);
            float im = __ldg(sib + x);
            amp[f] = dmul(pk2(re, im), tab[f << 1]);
        }
        rotTile<4>(amp, srot, 3, 0);
        rotShfl16(amp, srot, 4, s);
        #pragma unroll
        for (int f = 0; f < 16; f++){
            float x, y; upk2(amp[f], x, y);
            psi[(f << 10) | xbase] = make_float2(x, y);
        }
    }
    __syncthreads();
    passB<0>(psi, stab, srot, t);            __syncthreads();
    passC<0,false>(psi, stab, srot, t, 0);   __syncthreads();

    passA<1>(psi, stab, srot, t);            __syncthreads();
    passB<1>(psi, stab, srot, t);            __syncthreads();
    passC<1,false>(psi, stab, srot, t, 0);   __syncthreads();

    passA<2>(psi, stab, srot, t);            __syncthreads();
    passB<2>(psi, stab, srot, t);            __syncthreads();

    // ---- layer 2 pass C + measurement ----
    float zs[NW];
    #pragma unroll
    for (int w = 0; w < NW; w++) zs[w] = 0.f;
    passC<2,true>(psi, stab, srot, t, zs);

    // warp reduce
    #pragma unroll
    for (int off = 16; off > 0; off >>= 1)
        #pragma unroll
        for (int w = 0; w < NW; w++)
            zs[w] += __shfl_down_sync(0xffffffffu, zs[w], off);
    __syncthreads();
    float* red = (float*)psi;
    const int NWARP = NT/32;
    int lane = t & 31, wid = t >> 5;
    if (lane == 0){
        #pragma unroll
        for (int w = 0; w < NW; w++) red[w*NWARP + wid] = zs[w];
    }
    __syncthreads();
    if (t == 0){
        float acc = __ldg(hb);
        #pragma unroll
        for (int w = 0; w < NW; w++){
            float f = 0.f;
            #pragma unroll
            for (int r = 0; r < NWARP; r++) f += red[w*NWARP + r];
            acc += f * __ldg(hw + w);
        }
        out[b] = acc;
    }
}

// ---------------- launch ----------------

extern "C" void kernel_launch(void* const* d_in, const int* in_sizes, int n_in,
                              void* d_out, int out_size)
{
    const float* sr = (const float*)d_in[0];
    const float* si = (const float*)d_in[1];
    const float* vp = (const float*)d_in[2];
    const float* hw = (const float*)d_in[3];
    const float* hb = (const float*)d_in[4];
    float* out = (float*)d_out;

    const int SMEM = DIM*sizeof(float2) + NTAB*sizeof(float4) + 3*NW*sizeof(float2);

    cudaFuncSetAttribute(qsim_kernel, cudaFuncAttributeMaxDynamicSharedMemorySize, SMEM);

    setup_all<<<1, 1024>>>(vp);

    int B = in_sizes[0] / DIM;
    qsim_kernel<<<B, NT, SMEM>>>(sr, si, hw, hb, out);
}

// round 14
// speedup vs baseline: 1.2058x; 1.2058x over previous
#include <cuda_runtime.h>

// QuantumRegression: 1024 x 14-qubit statevector sim, 3 layers (Rot per wire + CNOT ring),
// <Z_w> features, linear head.
//
// R14 = R10 (proven 220.7us: 3-pass 5+5+4 @ NT=512, ZYZ with fully-deferred exit diagonals,
// frame-tracked CNOT perms, staggered pass C, Walsh measurement) with RY rotations done as
// 3-shear (lifting) Givens: u = v0 + p*v1; v1' = v1 + s*u; v0' = u + p*v1', p = -s/(1+c).
// 3 FMA2/pair instead of 4 -> ~20% less FMA-pipe work (the binding pipe).

#define NW   14
#define DIM  16384
#define NT   512

typedef unsigned long long u64;

// table offsets (float4 {c,c,-s,s})
#define OFF_A0  0        // 32    : layer0 entry A (deltas only), idx f
#define OFF_A1  32       // 2048  : layer1 entry A, idx (h<<6)|(f<<1)|t0
#define OFF_A2  2080     // 2048  : layer2 entry A
#define OFF_B0  4128     // 32    : layer0 entry B, idx f
#define OFF_B1  4160     // 512   : layer1 entry B, idx (f<<4)|q
#define OFF_B2  4672     // 512   : layer2 entry B
#define OFF_C   5184     // 3x16  : entry C per layer, idx m^u
#define NTAB    5232

__device__ float2 g_rot[3*NW];          // per-wire (p = -s/(1+c), s = sin g/2)
__device__ float4 g_tab[NTAB];

// ---------------- setup: ZYZ decomposition + deferred-diagonal tables ----------------

struct cpx { float re, im; };
__device__ __forceinline__ cpx cmul(cpx a, cpx b){
    cpx r; r.re = a.re*b.re - a.im*b.im; r.im = a.re*b.im + a.im*b.re; return r;
}

__device__ void rotmat(const float* p, cpx U[2][2]){
    float cx = cosf(0.5f*p[0]), sx = sinf(0.5f*p[0]);
    float cy = cosf(0.5f*p[1]), sy = sinf(0.5f*p[1]);
    float cz = cosf(0.5f*p[2]), sz = sinf(0.5f*p[2]);
    cpx r00 = { cy*cx,  sy*sx};
    cpx r01 = {-sy*cx, -cy*sx};
    cpx r10 = { sy*cx, -cy*sx};
    cpx r11 = { cy*cx, -sy*sx};
    cpx e0 = {cz, -sz}, e1 = {cz, sz};
    U[0][0] = cmul(e0, r00); U[0][1] = cmul(e0, r01);
    U[1][0] = cmul(e1, r10); U[1][1] = cmul(e1, r11);
}

__device__ __forceinline__ float angsum(const float* a, int w0, int bits, int nb){
    float s = 0.f;
    for (int k = 0; k < nb; k++){
        float h = 0.5f * a[w0 - k];
        s += ((bits >> k) & 1) ? h : -h;
    }
    return s;
}

__global__ void setup_all(const float* __restrict__ vp){
    __shared__ float sb[3*NW], sd[3*NW];
    int t = threadIdx.x;
    if (t < 3*NW){
        cpx U[2][2]; rotmat(vp + t*3, U);
        float na = hypotf(U[0][0].re, U[0][0].im);   // |cos g/2| (>=0)
        float nc = hypotf(U[1][0].re, U[1][0].im);   // |sin g/2| (>=0)
        float n  = hypotf(na, nc);
        // lifting parameters: p = -s/(1+c) = -nc/(n+na), s = nc/n
        g_rot[t] = make_float2(-nc/(n + na), nc/n);
        float beta, delta;
        if (nc > 1e-6f && na > 1e-6f){
            float aa = atan2f(U[0][0].im, U[0][0].re);
            float ac = atan2f(U[1][0].im, U[1][0].re);
            float ad = atan2f(U[1][1].im, U[1][1].re);
            beta = ac - aa; delta = ad - ac;
        } else if (nc <= 1e-6f){
            delta = 0.f;
            beta = atan2f(U[1][1].im, U[1][1].re) - atan2f(U[0][0].im, U[0][0].re);
        } else {
            delta = 0.f;
            beta = atan2f(U[1][0].im, U[1][0].re) - atan2f(-U[0][1].im, -U[0][1].re);
        }
        sb[t] = beta; sd[t] = delta;
    }
    __syncthreads();
    for (int idx = t; idx < NTAB; idx += blockDim.x){
        float ang;
        if (idx < OFF_A1){
            ang = angsum(sd, 0*NW + 4, idx, 5);
        } else if (idx < OFF_B0){
            int l = (idx < OFF_A2) ? 1 : 2;
            int r = idx - ((l == 1) ? OFF_A1 : OFF_A2);
            int h = r >> 6, f = (r >> 1) & 31, t0 = r & 1;
            int sA = (f ^ (f >> 1)) ^ (t0 ? 0x18 : 0);
            int sB = (h ^ (h >> 1)) ^ ((f & 1) ? 0x10 : 0);
            ang = angsum(sd, l*NW + 4, f, 5)
                + angsum(sb, (l-1)*NW + 4, sA, 5)
                + angsum(sb, (l-1)*NW + 9, sB, 5);
        } else if (idx < OFF_B1){
            ang = angsum(sd, 0*NW + 9, idx - OFF_B0, 5);
        } else if (idx < OFF_C){
            int l = (idx < OFF_B2) ? 1 : 2;
            int r = idx - ((l == 1) ? OFF_B1 : OFF_B2);
            int f = r >> 4, q = r & 15;
            int sC = (q ^ (q >> 1)) ^ ((f & 1) ? 8 : 0);
            ang = angsum(sd, l*NW + 9, f, 5)
                + angsum(sb, (l-1)*NW + 13, sC, 4);
        } else {
            int r = idx - OFF_C; int l = r >> 4, m = r & 15;
            ang = angsum(sd, l*NW + 13, m, 4);
        }
        float sp, cp; sincosf(ang, &sp, &cp);
        g_tab[idx] = make_float4(cp, cp, -sp, sp);
    }
}

// ---------------- packed f32x2 helpers ----------------

__device__ __forceinline__ u64 pk2(float lo, float hi){
    u64 r; asm("mov.b64 %0, {%1,%2};" : "=l"(r) : "f"(lo), "f"(hi)); return r;
}
__device__ __forceinline__ void upk2(u64 v, float& lo, float& hi){
    asm("mov.b64 {%0,%1}, %2;" : "=f"(lo), "=f"(hi) : "l"(v));
}
__device__ __forceinline__ u64 swp2(u64 v){
    u64 r;
    asm("{ .reg .b32 a,b; mov.b64 {a,b}, %1; mov.b64 %0, {b,a}; }" : "=l"(r) : "l"(v));
    return r;
}
__device__ __forceinline__ u64 f2(u64 a, u64 b, u64 c){
    u64 r; asm("fma.rn.f32x2 %0, %1, %2, %3;" : "=l"(r) : "l"(a), "l"(b), "l"(c)); return r;
}
__device__ __forceinline__ u64 m2(u64 a, u64 b){
    u64 r; asm("mul.rn.f32x2 %0, %1, %2;" : "=l"(r) : "l"(a), "l"(b)); return r;
}
__device__ __forceinline__ u64 dmul(u64 amp, float4 q){
    u64 uu = pk2(q.x, q.y), nn = pk2(q.z, q.w);
    return f2(uu, amp, m2(nn, swp2(amp)));
}

// NB RY rotations (3-shear lifting) on bits NB-1..0 of a 2^NB-amp tile; bit k <-> wire w0-k.
// u-bit set => 0/1 roles swapped => theta -> -theta => negate BOTH p and s.
template<int NB>
__device__ __forceinline__ void rotTile(u64* amp, const float2* rot, int w0, int u){
    #pragma unroll
    for (int k = NB-1; k >= 0; k--){
        float2 ps = rot[w0 - k];
        float p = ps.x, s = ps.y;
        if ((u >> k) & 1){ p = -p; s = -s; }
        u64 pp = pk2(p, p), ss = pk2(s, s);
        const int bit = 1 << k;
        #pragma unroll
        for (int q = 0; q < (1 << NB); q++)
            if (!(q & bit)){
                u64 v0 = amp[q], v1 = amp[q | bit];
                u64 uu = f2(pp, v1, v0);     // u   = v0 + p*v1
                u64 w1 = f2(ss, uu, v1);     // v1' = v1 + s*u
                amp[q | bit] = w1;
                amp[q]       = f2(pp, w1, uu); // v0' = u + p*v1'
            }
    }
}

// ---------------- CNOT-ring permutation (GF2 linear, constexpr-foldable) ----------------
__host__ __device__ __forceinline__ constexpr int cpfwd(int i){
    int y = i;
    y ^= y >> 1; y ^= y >> 2; y ^= y >> 4; y ^= y >> 8;
    return (y & 0x1FFF) ^ ((((y ^ (i >> 13)) & 1) << 13));
}
__host__ __device__ __forceinline__ constexpr int cpinv(int o){
    int t = o ^ (o >> 1);
    return (t & 0x1FFF) ^ (o & 0x2000) ^ ((o & 1) ? 0x3000 : 0);
}
template<int L>
__host__ __device__ __forceinline__ constexpr int pinvL(int x){
    return (L == 0) ? x : (L == 1) ? cpinv(x) : cpinv(cpinv(x));
}

// ---------------- passes ----------------

// pass A: logical bits 13..9 (wires 0..4), layer L. One 32-amp tile per thread.
template<int L>
__device__ __forceinline__ void passA(float2* psi, const float4* stab, const float2* srot, int t){
    const float4* tab = stab + ((L == 1) ? OFF_A1 : OFF_A2);
    const int ib = (((t >> 4) & 31) << 6) | (t & 1);
    int base = pinvL<L>(t);
    u64 amp[32];
    #pragma unroll
    for (int f = 0; f < 32; f++){
        float2 a = psi[base ^ pinvL<L>(f << 9)];
        amp[f] = dmul(pk2(a.x, a.y), tab[ib | (f << 1)]);
    }
    rotTile<5>(amp, srot, L*NW + 4, 0);
    #pragma unroll
    for (int f = 0; f < 32; f++){
        float xx, yy; upk2(amp[f], xx, yy);
        psi[base ^ pinvL<L>(f << 9)] = make_float2(xx, yy);
    }
}

// pass B: logical bits 8..4 (wires 5..9), layer L.
template<int L>
__device__ __forceinline__ void passB(float2* psi, const float4* stab, const float2* srot, int t){
    const float4* tab = stab + ((L == 0) ? OFF_B0 : (L == 1) ? OFF_B1 : OFF_B2)
                       + ((L == 0) ? 0 : (t & 15));
    int x = ((t >> 4) << 9) | (t & 15);
    int base = pinvL<L>(x);
    u64 amp[32];
    #pragma unroll
    for (int f = 0; f < 32; f++){
        float2 a = psi[base ^ pinvL<L>(f << 4)];
        amp[f] = dmul(pk2(a.x, a.y), (L == 0) ? tab[f] : tab[f << 4]);
    }
    rotTile<5>(amp, srot, L*NW + 9, 0);
    #pragma unroll
    for (int f = 0; f < 32; f++){
        float xx, yy; upk2(amp[f], xx, yy);
        psi[base ^ pinvL<L>(f << 4)] = make_float2(xx, yy);
    }
}

// stagger offset u for C passes: u = A_L^{-1}((lane&15) ^ base_low4)
template<int L>
__device__ __forceinline__ int p3stagger(int t){
    int r4 = t & 15;
    if (L == 0) return r4;
    if (L == 1){ int v = r4 ^ ((t & 1) << 3); return (v ^ (v>>1) ^ (v>>2) ^ (v>>3)) & 15; }
    int v = r4 ^ ((t & 3) << 2); return (v ^ (v >> 2)) & 15;
}

// pass C: logical bits 3..0 (wires 10..13), layer L; entry table only (exits deferred).
// MEAS folds P^3 measurement with partial Walsh butterfly.
template<int L, bool MEAS>
__device__ __forceinline__ void passC(float2* psi, const float4* stab, const float2* srot,
                                      int t, float* zs){
    const float4* tabC = stab + OFF_C + L*16;
    const int u = p3stagger<L>(t);
    const int uoff = pinvL<L>(u);
    #pragma unroll 1
    for (int tt = 0; tt < DIM/16/NT; tt++){
        int y = t + NT*tt;                        // 10-bit tile index (logical bits 13..4)
        int base = pinvL<L>(y << 4) ^ uoff;
        u64 amp[16];
        #pragma unroll
        for (int m = 0; m < 16; m++){
            float2 a = psi[base ^ pinvL<L>(m)];
            amp[m] = dmul(pk2(a.x, a.y), tabC[m ^ u]);
        }
        rotTile<4>(amp, srot, L*NW + 13, u);
        if (!MEAS){
            #pragma unroll
            for (int m = 0; m < 16; m++){
                float xx, yy; upk2(amp[m], xx, yy);
                psi[base ^ pinvL<L>(m)] = make_float2(xx, yy);
            }
        } else {
            // logical o = cpfwd((y<<4) ^ u ^ m); cpfwd(m) sign bits live in o bits 3..0,13
            int obase = cpfwd((y << 4) ^ u);
            float pr[16];
            #pragma unroll
            for (int m = 0; m < 16; m++){
                float xx, yy; upk2(amp[m], xx, yy);
                pr[m] = xx*xx + yy*yy;
            }
            // partial Walsh butterfly over m bits b0..b3:
            //   o bit0 = b0^b1^b2^b3 (also bit13), bit1 = b1^b2^b3, bit2 = b2^b3, bit3 = b3
            float P[8], Mv[8];
            #pragma unroll
            for (int j = 0; j < 8; j++){ P[j] = pr[2*j] + pr[2*j+1]; Mv[j] = pr[2*j] - pr[2*j+1]; }
            float Spar = Mv[0]-Mv[1]-Mv[2]+Mv[3]-Mv[4]+Mv[5]+Mv[6]-Mv[7];
            float PP[4], PM[4];
            #pragma unroll
            for (int k = 0; k < 4; k++){ PP[k] = P[2*k] + P[2*k+1]; PM[k] = P[2*k] - P[2*k+1]; }
            float S123 = PM[0]-PM[1]-PM[2]+PM[3];
            float PPP0 = PP[0]+PP[1], PPP1 = PP[2]+PP[3];
            float S23  = (PP[0]-PP[1]) - (PP[2]-PP[3]);
            float T    = PPP0 + PPP1;
            float S3   = PPP0 - PPP1;
            #pragma unroll
            for (int w = 1; w <= 9; w++){
                unsigned msk = ((unsigned)obase << (18 + w)) & 0x80000000u;
                zs[w] += __uint_as_float(__float_as_uint(T) ^ msk);
            }
            zs[0]  += __uint_as_float(__float_as_uint(Spar) ^ (((unsigned)obase << 18) & 0x80000000u));
            zs[13] += __uint_as_float(__float_as_uint(Spar) ^ (((unsigned)obase << 31) & 0x80000000u));
            zs[12] += __uint_as_float(__float_as_uint(S123) ^ (((unsigned)obase << 30) & 0x80000000u));
            zs[11] += __uint_as_float(__float_as_uint(S23)  ^ (((unsigned)obase << 29) & 0x80000000u));
            zs[10] += __uint_as_float(__float_as_uint(S3)   ^ (((unsigned)obase << 28) & 0x80000000u));
        }
    }
}

// ---------------- main kernel ----------------

__global__ void __launch_bounds__(NT, 1)
qsim_kernel(const float* __restrict__ sr, const float* __restrict__ si,
            const float* __restrict__ hw, const float* __restrict__ hb,
            float* __restrict__ out)
{
    extern __shared__ float2 sm[];
    float2* psi = sm;
    float4* stab = reinterpret_cast<float4*>(sm + DIM);
    float2* srot = reinterpret_cast<float2*>(stab + NTAB);
    const int t = threadIdx.x;
    const int b = blockIdx.x;

    #pragma unroll 1
    for (int i = t; i < NTAB; i += NT) stab[i] = g_tab[i];
    if (t < 3*NW) srot[t] = g_rot[t];
    __syncthreads();

    // ---- layer 0 pass A fused with global load ----
    {
        const float* srb = sr + (size_t)b * DIM;
        const float* sib = si + (size_t)b * DIM;
        const float4* tab = stab + OFF_A0;
        u64 amp[32];
        #pragma unroll
        for (int f = 0; f < 32; f++){
            float re = __ldg(srb + (f << 9) + t);
            float im = __ldg(sib + (f << 9) + t);
            amp[f] = dmul(pk2(re, im), tab[f]);
        }
        rotTile<5>(amp, srot, 4, 0);
        #pragma unroll
        for (int f = 0; f < 32; f++){
            float x, y; upk2(amp[f], x, y);
            psi[(f << 9) + t] = make_float2(x, y);
        }
    }
    __syncthreads();
    passB<0>(psi, stab, srot, t);            __syncthreads();
    passC<0,false>(psi, stab, srot, t, 0);   __syncthreads();

    passA<1>(psi, stab, srot, t);            __syncthreads();
    passB<1>(psi, stab, srot, t);            __syncthreads();
    passC<1,false>(psi, stab, srot, t, 0);   __syncthreads();

    passA<2>(psi, stab, srot, t);            __syncthreads();
    passB<2>(psi, stab, srot, t);            __syncthreads();

    // ---- layer 2 pass C + measurement (P^3 folded; all exit diagonals dropped) ----
    float zs[NW];
    #pragma unroll
    for (int w = 0; w < NW; w++) zs[w] = 0.f;
    passC<2,true>(psi, stab, srot, t, zs);

    // warp reduce
    #pragma unroll
    for (int off = 16; off > 0; off >>= 1)
        #pragma unroll
        for (int w = 0; w < NW; w++)
            zs[w] += __shfl_down_sync(0xffffffffu, zs[w], off);
    __syncthreads();
    float* red = (float*)psi;
    const int NWARP = NT/32;
    int lane = t & 31, wid = t >> 5;
    if (lane == 0){
        #pragma unroll
        for (int w = 0; w < NW; w++) red[w*NWARP + wid] = zs[w];
    }
    __syncthreads();
    if (t == 0){
        float acc = __ldg(hb);
        #pragma unroll
        for (int w = 0; w < NW; w++){
            float f = 0.f;
            #pragma unroll
            for (int r = 0; r < NWARP; r++) f += red[w*NWARP + r];
            acc += f * __ldg(hw + w);
        }
        out[b] = acc;
    }
}

// ---------------- launch ----------------

extern "C" void kernel_launch(void* const* d_in, const int* in_sizes, int n_in,
                              void* d_out, int out_size)
{
    const float* sr = (const float*)d_in[0];
    const float* si = (const float*)d_in[1];
    const float* vp = (const float*)d_in[2];
    const float* hw = (const float*)d_in[3];
    const float* hb = (const float*)d_in[4];
    float* out = (float*)d_out;

    const int SMEM = DIM*sizeof(float2) + NTAB*sizeof(float4) + 3*NW*sizeof(float2);

    cudaFuncSetAttribute(qsim_kernel, cudaFuncAttributeMaxDynamicSharedMemorySize, SMEM);

    setup_all<<<1, 1024>>>(vp);

    int B = in_sizes[0] / DIM;
    qsim_kernel<<<B, NT, SMEM>>>(sr, si, hw, hb, out);
}

// round 15
// speedup vs baseline: 1.6217x; 1.3449x over previous
#include <cuda_runtime.h>
#include <cuda_fp16.h>

// QuantumRegression: 1024 x 14-qubit statevector sim, 3 layers (Rot per wire + CNOT ring),
// <Z_w> features, linear head.
//
// R15 = R14 (3-pass 5+5+4, ZYZ shear rotations, deferred diagonals, frame-tracked perms,
// Walsh measurement) with the state stored as fp16 (half2 per amp) in smem:
//  - crossbar bytes halved; tables stored as float2 (c,s) -> smem 107KB -> 2 CTAs/SM
//  - NT=256, __launch_bounds__(256,2): cross-CTA overlap hides barrier/LDS latency
//  - linear smem swizzle a ^= (a>>5)&0x10 keeps 4-byte-bank accesses conflict-free
//  - diagonals applied as 4 scalar FMA on unpacked floats (no packed-const build)

#define NW   14
#define DIM  16384
#define NT   256

typedef unsigned long long u64;
typedef unsigned int u32;

// table offsets (float2 {c,s})
#define OFF_A0  0        // 32    : layer0 entry A (deltas only), idx f
#define OFF_A1  32       // 2048  : layer1 entry A, idx (h<<6)|(f<<1)|t0
#define OFF_A2  2080     // 2048  : layer2 entry A
#define OFF_B0  4128     // 32    : layer0 entry B, idx f
#define OFF_B1  4160     // 512   : layer1 entry B, idx (f<<4)|q
#define OFF_B2  4672     // 512   : layer2 entry B
#define OFF_C   5184     // 3x16  : entry C per layer, idx m^u
#define NTAB    5232

__device__ float2 g_rot[3*NW];          // per-wire (p = -s/(1+c), s = sin g/2)
__device__ float2 g_tab[NTAB];          // phase (c, s)

// ---------------- setup: ZYZ decomposition + deferred-diagonal tables ----------------

struct cpx { float re, im; };
__device__ __forceinline__ cpx cmul(cpx a, cpx b){
    cpx r; r.re = a.re*b.re - a.im*b.im; r.im = a.re*b.im + a.im*b.re; return r;
}

__device__ void rotmat(const float* p, cpx U[2][2]){
    float cx = cosf(0.5f*p[0]), sx = sinf(0.5f*p[0]);
    float cy = cosf(0.5f*p[1]), sy = sinf(0.5f*p[1]);
    float cz = cosf(0.5f*p[2]), sz = sinf(0.5f*p[2]);
    cpx r00 = { cy*cx,  sy*sx};
    cpx r01 = {-sy*cx, -cy*sx};
    cpx r10 = { sy*cx, -cy*sx};
    cpx r11 = { cy*cx, -sy*sx};
    cpx e0 = {cz, -sz}, e1 = {cz, sz};
    U[0][0] = cmul(e0, r00); U[0][1] = cmul(e0, r01);
    U[1][0] = cmul(e1, r10); U[1][1] = cmul(e1, r11);
}

__device__ __forceinline__ float angsum(const float* a, int w0, int bits, int nb){
    float s = 0.f;
    for (int k = 0; k < nb; k++){
        float h = 0.5f * a[w0 - k];
        s += ((bits >> k) & 1) ? h : -h;
    }
    return s;
}

__global__ void setup_all(const float* __restrict__ vp){
    __shared__ float sb[3*NW], sd[3*NW];
    int t = threadIdx.x;
    if (t < 3*NW){
        cpx U[2][2]; rotmat(vp + t*3, U);
        float na = hypotf(U[0][0].re, U[0][0].im);   // |cos g/2|
        float nc = hypotf(U[1][0].re, U[1][0].im);   // |sin g/2|
        float n  = hypotf(na, nc);
        g_rot[t] = make_float2(-nc/(n + na), nc/n);  // (p, s)
        float beta, delta;
        if (nc > 1e-6f && na > 1e-6f){
            float aa = atan2f(U[0][0].im, U[0][0].re);
            float ac = atan2f(U[1][0].im, U[1][0].re);
            float ad = atan2f(U[1][1].im, U[1][1].re);
            beta = ac - aa; delta = ad - ac;
        } else if (nc <= 1e-6f){
            delta = 0.f;
            beta = atan2f(U[1][1].im, U[1][1].re) - atan2f(U[0][0].im, U[0][0].re);
        } else {
            delta = 0.f;
            beta = atan2f(U[1][0].im, U[1][0].re) - atan2f(-U[0][1].im, -U[0][1].re);
        }
        sb[t] = beta; sd[t] = delta;
    }
    __syncthreads();
    for (int idx = t; idx < NTAB; idx += blockDim.x){
        float ang;
        if (idx < OFF_A1){
            ang = angsum(sd, 0*NW + 4, idx, 5);
        } else if (idx < OFF_B0){
            int l = (idx < OFF_A2) ? 1 : 2;
            int r = idx - ((l == 1) ? OFF_A1 : OFF_A2);
            int h = r >> 6, f = (r >> 1) & 31, t0 = r & 1;
            int sA = (f ^ (f >> 1)) ^ (t0 ? 0x18 : 0);
            int sB = (h ^ (h >> 1)) ^ ((f & 1) ? 0x10 : 0);
            ang = angsum(sd, l*NW + 4, f, 5)
                + angsum(sb, (l-1)*NW + 4, sA, 5)
                + angsum(sb, (l-1)*NW + 9, sB, 5);
        } else if (idx < OFF_B1){
            ang = angsum(sd, 0*NW + 9, idx - OFF_B0, 5);
        } else if (idx < OFF_C){
            int l = (idx < OFF_B2) ? 1 : 2;
            int r = idx - ((l == 1) ? OFF_B1 : OFF_B2);
            int f = r >> 4, q = r & 15;
            int sC = (q ^ (q >> 1)) ^ ((f & 1) ? 8 : 0);
            ang = angsum(sd, l*NW + 9, f, 5)
                + angsum(sb, (l-1)*NW + 13, sC, 4);
        } else {
            int r = idx - OFF_C; int l = r >> 4, m = r & 15;
            ang = angsum(sd, l*NW + 13, m, 4);
        }
        float sp, cp; sincosf(ang, &sp, &cp);
        g_tab[idx] = make_float2(cp, sp);
    }
}

// ---------------- packed f32x2 helpers ----------------

__device__ __forceinline__ u64 pk2(float lo, float hi){
    u64 r; asm("mov.b64 %0, {%1,%2};" : "=l"(r) : "f"(lo), "f"(hi)); return r;
}
__device__ __forceinline__ void upk2(u64 v, float& lo, float& hi){
    asm("mov.b64 {%0,%1}, %2;" : "=f"(lo), "=f"(hi) : "l"(v));
}
__device__ __forceinline__ u64 f2(u64 a, u64 b, u64 c){
    u64 r; asm("fma.rn.f32x2 %0, %1, %2, %3;" : "=l"(r) : "l"(a), "l"(b), "l"(c)); return r;
}
__device__ __forceinline__ u64 m2(u64 a, u64 b){
    u64 r; asm("mul.rn.f32x2 %0, %1, %2;" : "=l"(r) : "l"(a), "l"(b)); return r;
}

// load half2 amp, apply phase (c,s) with scalar FMAs, return packed f32x2
__device__ __forceinline__ u64 ldamp(const u32* psi, int a, float2 q){
    __half2 h = *reinterpret_cast<const __half2*>(&psi[a]);
    float2 v = __half22float2(h);
    float xr = fmaf(q.x, v.x, -q.y * v.y);
    float yi = fmaf(q.x, v.y,  q.y * v.x);
    return pk2(xr, yi);
}
__device__ __forceinline__ void stamp(u32* psi, int a, u64 amp){
    float x, y; upk2(amp, x, y);
    __half2 h = __float22half2_rn(make_float2(x, y));
    psi[a] = *reinterpret_cast<u32*>(&h);
}

// NB RY rotations (3-shear lifting) on bits NB-1..0 of a 2^NB-amp tile; bit k <-> wire w0-k.
template<int NB>
__device__ __forceinline__ void rotTile(u64* amp, const float2* rot, int w0, int u){
    #pragma unroll
    for (int k = NB-1; k >= 0; k--){
        float2 ps = rot[w0 - k];
        float p = ps.x, s = ps.y;
        if ((u >> k) & 1){ p = -p; s = -s; }
        u64 pp = pk2(p, p), ss = pk2(s, s);
        const int bit = 1 << k;
        #pragma unroll
        for (int q = 0; q < (1 << NB); q++)
            if (!(q & bit)){
                u64 v0 = amp[q], v1 = amp[q | bit];
                u64 uu = f2(pp, v1, v0);       // u   = v0 + p*v1
                u64 w1 = f2(ss, uu, v1);       // v1' = v1 + s*u
                amp[q | bit] = w1;
                amp[q]       = f2(pp, w1, uu); // v0' = u + p*v1'
            }
    }
}

// ---------------- CNOT-ring permutation + smem swizzle (GF2 linear) ----------------
__host__ __device__ __forceinline__ constexpr int cpfwd(int i){
    int y = i;
    y ^= y >> 1; y ^= y >> 2; y ^= y >> 4; y ^= y >> 8;
    return (y & 0x1FFF) ^ ((((y ^ (i >> 13)) & 1) << 13));
}
__host__ __device__ __forceinline__ constexpr int cpinv(int o){
    int t = o ^ (o >> 1);
    return (t & 0x1FFF) ^ (o & 0x2000) ^ ((o & 1) ? 0x3000 : 0);
}
template<int L>
__host__ __device__ __forceinline__ constexpr int pinvL(int x){
    return (L == 0) ? x : (L == 1) ? cpinv(x) : cpinv(cpinv(x));
}
// linear bank swizzle: XOR bit 9 into bit 4 (fixes 4B-bank conflicts; self-composing)
__host__ __device__ __forceinline__ constexpr int sw(int a){
    return a ^ ((a >> 5) & 0x10);
}

// ---------------- passes ----------------

// pass A: logical bits 13..9 (wires 0..4), layer L>=1. Tiles tau = t + NT*it.
template<int L>
__device__ __forceinline__ void passA(u32* psi, const float2* stab, const float2* srot, int t){
    #pragma unroll 1
    for (int it = 0; it < 2; it++){
        int tau = t + NT*it;
        const float2* tab = stab + ((L == 1) ? OFF_A1 : OFF_A2)
                          + (((tau >> 4) & 31) << 6) + (tau & 1);
        int base = sw(pinvL<L>(tau));
        u64 amp[32];
        #pragma unroll
        for (int f = 0; f < 32; f++)
            amp[f] = ldamp(psi, base ^ sw(pinvL<L>(f << 9)), tab[f << 1]);
        rotTile<5>(amp, srot, L*NW + 4, 0);
        #pragma unroll
        for (int f = 0; f < 32; f++)
            stamp(psi, base ^ sw(pinvL<L>(f << 9)), amp[f]);
    }
}

// pass B: logical bits 8..4 (wires 5..9), layer L.
template<int L>
__device__ __forceinline__ void passB(u32* psi, const float2* stab, const float2* srot, int t){
    #pragma unroll 1
    for (int it = 0; it < 2; it++){
        int tau = t + NT*it;
        int q = tau & 15;
        int base = sw(pinvL<L>(((tau >> 4) << 9) | q));
        u64 amp[32];
        if (L == 0){
            const float2* tab = stab + OFF_B0;
            #pragma unroll
            for (int f = 0; f < 32; f++)
                amp[f] = ldamp(psi, base ^ sw(pinvL<L>(f << 4)), tab[f]);
        } else {
            const float2* tab = stab + ((L == 1) ? OFF_B1 : OFF_B2) + q;
            #pragma unroll
            for (int f = 0; f < 32; f++)
                amp[f] = ldamp(psi, base ^ sw(pinvL<L>(f << 4)), tab[f << 4]);
        }
        rotTile<5>(amp, srot, L*NW + 9, 0);
        #pragma unroll
        for (int f = 0; f < 32; f++)
            stamp(psi, base ^ sw(pinvL<L>(f << 4)), amp[f]);
    }
}

// stagger offset u for C passes; extra ^((t>>4)&1) differentiates half-warps (4B banks)
template<int L>
__device__ __forceinline__ int p3stagger(int t){
    int r4 = t & 15;
    int hw = (t >> 4) & 1;
    if (L == 0) return r4 ^ hw;
    if (L == 1){ int v = r4 ^ ((t & 1) << 3); return ((v ^ (v>>1) ^ (v>>2) ^ (v>>3)) & 15) ^ hw; }
    int v = r4 ^ ((t & 3) << 2); return ((v ^ (v >> 2)) & 15) ^ hw;
}

// pass C: logical bits 3..0 (wires 10..13), layer L; entry table only (exits deferred).
// MEAS folds P^3 measurement with partial Walsh butterfly.
template<int L, bool MEAS>
__device__ __forceinline__ void passC(u32* psi, const float2* stab, const float2* srot,
                                      int t, float* zs){
    const float2* tabC = stab + OFF_C + L*16;
    const int u = p3stagger<L>(t);
    const int uoff = sw(pinvL<L>(u));
    #pragma unroll 1
    for (int tt = 0; tt < 4; tt++){
        int y = t + NT*tt;                        // 10-bit tile index (logical bits 13..4)
        int base = sw(pinvL<L>(y << 4)) ^ uoff;
        u64 amp[16];
        #pragma unroll
        for (int m = 0; m < 16; m++)
            amp[m] = ldamp(psi, base ^ sw(pinvL<L>(m)), tabC[m ^ u]);
        rotTile<4>(amp, srot, L*NW + 13, u);
        if (!MEAS){
            #pragma unroll
            for (int m = 0; m < 16; m++)
                stamp(psi, base ^ sw(pinvL<L>(m)), amp[m]);
        } else {
            // logical o = cpfwd((y<<4) ^ u ^ m); cpfwd(m) sign bits live in o bits 3..0,13
            int obase = cpfwd((y << 4) ^ u);
            float pr[16];
            #pragma unroll
            for (int m = 0; m < 16; m++){
                float xx, yy; upk2(amp[m], xx, yy);
                pr[m] = xx*xx + yy*yy;
            }
            float P[8], Mv[8];
            #pragma unroll
            for (int j = 0; j < 8; j++){ P[j] = pr[2*j] + pr[2*j+1]; Mv[j] = pr[2*j] - pr[2*j+1]; }
            float Spar = Mv[0]-Mv[1]-Mv[2]+Mv[3]-Mv[4]+Mv[5]+Mv[6]-Mv[7];
            float PP[4], PM[4];
            #pragma unroll
            for (int k = 0; k < 4; k++){ PP[k] = P[2*k] + P[2*k+1]; PM[k] = P[2*k] - P[2*k+1]; }
            float S123 = PM[0]-PM[1]-PM[2]+PM[3];
            float PPP0 = PP[0]+PP[1], PPP1 = PP[2]+PP[3];
            float S23  = (PP[0]-PP[1]) - (PP[2]-PP[3]);
            float T    = PPP0 + PPP1;
            float S3   = PPP0 - PPP1;
            #pragma unroll
            for (int w = 1; w <= 9; w++){
                unsigned msk = ((unsigned)obase << (18 + w)) & 0x80000000u;
                zs[w] += __uint_as_float(__float_as_uint(T) ^ msk);
            }
            zs[0]  += __uint_as_float(__float_as_uint(Spar) ^ (((unsigned)obase << 18) & 0x80000000u));
            zs[13] += __uint_as_float(__float_as_uint(Spar) ^ (((unsigned)obase << 31) & 0x80000000u));
            zs[12] += __uint_as_float(__float_as_uint(S123) ^ (((unsigned)obase << 30) & 0x80000000u));
            zs[11] += __uint_as_float(__float_as_uint(S23)  ^ (((unsigned)obase << 29) & 0x80000000u));
            zs[10] += __uint_as_float(__float_as_uint(S3)   ^ (((unsigned)obase << 28) & 0x80000000u));
        }
    }
}

// ---------------- main kernel ----------------

__global__ void __launch_bounds__(NT, 2)
qsim_kernel(const float* __restrict__ sr, const float* __restrict__ si,
            const float* __restrict__ hw, const float* __restrict__ hb,
            float* __restrict__ out)
{
    extern __shared__ u32 smu[];
    u32* psi = smu;                                           // half2 per amp
    float2* stab = reinterpret_cast<float2*>(smu + DIM);      // NTAB float2
    float2* srot = stab + NTAB;                               // 42 float2
    const int t = threadIdx.x;
    const int b = blockIdx.x;

    #pragma unroll 1
    for (int i = t; i < NTAB; i += NT) stab[i] = g_tab[i];
    if (t < 3*NW) srot[t] = g_rot[t];
    __syncthreads();

    // ---- layer 0 pass A fused with global load ----
    {
        const float* srb = sr + (size_t)b * DIM;
        const float* sib = si + (size_t)b * DIM;
        const float2* tab = stab + OFF_A0;
        #pragma unroll 1
        for (int it = 0; it < 2; it++){
            int tau = t + NT*it;
            u64 amp[32];
            #pragma unroll
            for (int f = 0; f < 32; f++){
                float re = __ldg(srb + (f << 9) + tau);
                float im = __ldg(sib + (f << 9) + tau);
                float2 q = tab[f];
                float xr = fmaf(q.x, re, -q.y * im);
                float yi = fmaf(q.x, im,  q.y * re);
                amp[f] = pk2(xr, yi);
            }
            rotTile<5>(amp, srot, 4, 0);
            #pragma unroll
            for (int f = 0; f < 32; f++)
                stamp(psi, tau ^ sw(f << 9), amp[f]);
        }
    }
    __syncthreads();
    passB<0>(psi, stab, srot, t);            __syncthreads();
    passC<0,false>(psi, stab, srot, t, 0);   __syncthreads();

    passA<1>(psi, stab, srot, t);            __syncthreads();
    passB<1>(psi, stab, srot, t);            __syncthreads();
    passC<1,false>(psi, stab, srot, t, 0);   __syncthreads();

    passA<2>(psi, stab, srot, t);            __syncthreads();
    passB<2>(psi, stab, srot, t);            __syncthreads();

    // ---- layer 2 pass C + measurement (P^3 folded; all exit diagonals dropped) ----
    float zs[NW];
    #pragma unroll
    for (int w = 0; w < NW; w++) zs[w] = 0.f;
    passC<2,true>(psi, stab, srot, t, zs);

    // warp reduce
    #pragma unroll
    for (int off = 16; off > 0; off >>= 1)
        #pragma unroll
        for (int w = 0; w < NW; w++)
            zs[w] += __shfl_down_sync(0xffffffffu, zs[w], off);
    __syncthreads();                       // all psi reads done; reuse as scratch
    float* red = reinterpret_cast<float*>(psi);
    const int NWARP = NT/32;
    int lane = t & 31, wid = t >> 5;
    if (lane == 0){
        #pragma unroll
        for (int w = 0; w < NW; w++) red[w*NWARP + wid] = zs[w];
    }
    __syncthreads();
    if (t == 0){
        float acc = __ldg(hb);
        #pragma unroll
        for (int w = 0; w < NW; w++){
            float f = 0.f;
            #pragma unroll
            for (int r = 0; r < NWARP; r++) f += red[w*NWARP + r];
            acc += f * __ldg(hw + w);
        }
        out[b] = acc;
    }
}

// ---------------- launch ----------------

extern "C" void kernel_launch(void* const* d_in, const int* in_sizes, int n_in,
                              void* d_out, int out_size)
{
    const float* sr = (const float*)d_in[0];
    const float* si = (const float*)d_in[1];
    const float* vp = (const float*)d_in[2];
    const float* hw = (const float*)d_in[3];
    const float* hb = (const float*)d_in[4];
    float* out = (float*)d_out;

    const int SMEM = DIM*sizeof(u32) + NTAB*sizeof(float2) + 3*NW*sizeof(float2);

    cudaFuncSetAttribute(qsim_kernel, cudaFuncAttributeMaxDynamicSharedMemorySize, SMEM);

    setup_all<<<1, 1024>>>(vp);

    int B = in_sizes[0] / DIM;
    qsim_kernel<<<B, NT, SMEM>>>(sr, si, hw, hb, out);
}

// round 16
// speedup vs baseline: 1.6889x; 1.0415x over previous
#include <cuda_runtime.h>
#include <cuda_fp16.h>

// QuantumRegression: 1024 x 14-qubit statevector sim, 3 layers (Rot per wire + CNOT ring),
// <Z_w> features, linear head.
//
// R16 = R15 (fp16 state in smem, 2 CTAs/SM, 3-pass 5+5+4, ZYZ shear rotations, deferred
// diagonals, frame-tracked perms, Walsh measurement) with pass C's diagonal ELIMINATED:
// deltaC(L) depends only on logical bits 3..0 = pass B's per-thread base q, and commutes
// with pass B's rotations (disjoint bits), so it folds into pass B's entry table
// (idx (f<<4)|q for ALL layers). Pass C = raw load, rotate, store: no table, no dmul.

#define NW   14
#define DIM  16384
#define NT   256

typedef unsigned long long u64;
typedef unsigned int u32;

// table offsets (float2 {c,s})
#define OFF_A0  0        // 32    : layer0 entry A (deltaA), idx f
#define OFF_A1  32       // 2048  : layer1 entry A, idx (h<<6)|(f<<1)|t0
#define OFF_A2  2080     // 2048  : layer2 entry A
#define OFF_B0  4128     // 3x512 : entry B per layer, idx (L<<9)|(f<<4)|q
                         //         = deltaB(L,f) + deltaC(L,q) [+ betaC(L-1) for L>=1]
#define NTAB    5664

__device__ float2 g_rot[3*NW];          // per-wire (p = -s/(1+c), s = sin g/2)
__device__ float2 g_tab[NTAB];          // phase (c, s)

// ---------------- setup: ZYZ decomposition + deferred-diagonal tables ----------------

struct cpx { float re, im; };
__device__ __forceinline__ cpx cmul(cpx a, cpx b){
    cpx r; r.re = a.re*b.re - a.im*b.im; r.im = a.re*b.im + a.im*b.re; return r;
}

__device__ void rotmat(const float* p, cpx U[2][2]){
    float cx = cosf(0.5f*p[0]), sx = sinf(0.5f*p[0]);
    float cy = cosf(0.5f*p[1]), sy = sinf(0.5f*p[1]);
    float cz = cosf(0.5f*p[2]), sz = sinf(0.5f*p[2]);
    cpx r00 = { cy*cx,  sy*sx};
    cpx r01 = {-sy*cx, -cy*sx};
    cpx r10 = { sy*cx, -cy*sx};
    cpx r11 = { cy*cx, -sy*sx};
    cpx e0 = {cz, -sz}, e1 = {cz, sz};
    U[0][0] = cmul(e0, r00); U[0][1] = cmul(e0, r01);
    U[1][0] = cmul(e1, r10); U[1][1] = cmul(e1, r11);
}

__device__ __forceinline__ float angsum(const float* a, int w0, int bits, int nb){
    float s = 0.f;
    for (int k = 0; k < nb; k++){
        float h = 0.5f * a[w0 - k];
        s += ((bits >> k) & 1) ? h : -h;
    }
    return s;
}

__global__ void setup_all(const float* __restrict__ vp){
    __shared__ float sb[3*NW], sd[3*NW];
    int t = threadIdx.x;
    if (t < 3*NW){
        cpx U[2][2]; rotmat(vp + t*3, U);
        float na = hypotf(U[0][0].re, U[0][0].im);   // |cos g/2|
        float nc = hypotf(U[1][0].re, U[1][0].im);   // |sin g/2|
        float n  = hypotf(na, nc);
        g_rot[t] = make_float2(-nc/(n + na), nc/n);  // (p, s)
        float beta, delta;
        if (nc > 1e-6f && na > 1e-6f){
            float aa = atan2f(U[0][0].im, U[0][0].re);
            float ac = atan2f(U[1][0].im, U[1][0].re);
            float ad = atan2f(U[1][1].im, U[1][1].re);
            beta = ac - aa; delta = ad - ac;
        } else if (nc <= 1e-6f){
            delta = 0.f;
            beta = atan2f(U[1][1].im, U[1][1].re) - atan2f(U[0][0].im, U[0][0].re);
        } else {
            delta = 0.f;
            beta = atan2f(U[1][0].im, U[1][0].re) - atan2f(-U[0][1].im, -U[0][1].re);
        }
        sb[t] = beta; sd[t] = delta;
    }
    __syncthreads();
    for (int idx = t; idx < NTAB; idx += blockDim.x){
        float ang;
        if (idx < OFF_A1){                       // layer0 entry A: deltaA
            ang = angsum(sd, 0*NW + 4, idx, 5);
        } else if (idx < OFF_B0){                // entry A layers 1,2
            int l = (idx < OFF_A2) ? 1 : 2;
            int r = idx - ((l == 1) ? OFF_A1 : OFF_A2);
            int h = r >> 6, f = (r >> 1) & 31, t0 = r & 1;
            int sA = (f ^ (f >> 1)) ^ (t0 ? 0x18 : 0);
            int sB = (h ^ (h >> 1)) ^ ((f & 1) ? 0x10 : 0);
            ang = angsum(sd, l*NW + 4, f, 5)
                + angsum(sb, (l-1)*NW + 4, sA, 5)
                + angsum(sb, (l-1)*NW + 9, sB, 5);
        } else {                                 // entry B, layers 0..2: idx (l<<9)|(f<<4)|q
            int r = idx - OFF_B0;
            int l = r >> 9; r &= 511;
            int f = r >> 4, q = r & 15;
            ang = angsum(sd, l*NW + 9, f, 5)     // deltaB(L)
                + angsum(sd, l*NW + 13, q, 4);   // deltaC(L)  (moved out of pass C)
            if (l >= 1){
                int sC = (q ^ (q >> 1)) ^ ((f & 1) ? 8 : 0);
                ang += angsum(sb, (l-1)*NW + 13, sC, 4);   // betaC(L-1)
            }
        }
        float sp, cp; sincosf(ang, &sp, &cp);
        g_tab[idx] = make_float2(cp, sp);
    }
}

// ---------------- packed f32x2 helpers ----------------

__device__ __forceinline__ u64 pk2(float lo, float hi){
    u64 r; asm("mov.b64 %0, {%1,%2};" : "=l"(r) : "f"(lo), "f"(hi)); return r;
}
__device__ __forceinline__ void upk2(u64 v, float& lo, float& hi){
    asm("mov.b64 {%0,%1}, %2;" : "=f"(lo), "=f"(hi) : "l"(v));
}
__device__ __forceinline__ u64 f2(u64 a, u64 b, u64 c){
    u64 r; asm("fma.rn.f32x2 %0, %1, %2, %3;" : "=l"(r) : "l"(a), "l"(b), "l"(c)); return r;
}
__device__ __forceinline__ u64 m2(u64 a, u64 b){
    u64 r; asm("mul.rn.f32x2 %0, %1, %2;" : "=l"(r) : "l"(a), "l"(b)); return r;
}

// load half2 amp, apply phase (c,s) with scalar FMAs, return packed f32x2
__device__ __forceinline__ u64 ldamp(const u32* psi, int a, float2 q){
    __half2 h = *reinterpret_cast<const __half2*>(&psi[a]);
    float2 v = __half22float2(h);
    float xr = fmaf(q.x, v.x, -q.y * v.y);
    float yi = fmaf(q.x, v.y,  q.y * v.x);
    return pk2(xr, yi);
}
// raw load (no phase)
__device__ __forceinline__ u64 ldraw(const u32* psi, int a){
    __half2 h = *reinterpret_cast<const __half2*>(&psi[a]);
    float2 v = __half22float2(h);
    return pk2(v.x, v.y);
}
__device__ __forceinline__ void stamp(u32* psi, int a, u64 amp){
    float x, y; upk2(amp, x, y);
    __half2 h = __float22half2_rn(make_float2(x, y));
    psi[a] = *reinterpret_cast<u32*>(&h);
}

// NB RY rotations (3-shear lifting) on bits NB-1..0 of a 2^NB-amp tile; bit k <-> wire w0-k.
template<int NB>
__device__ __forceinline__ void rotTile(u64* amp, const float2* rot, int w0, int u){
    #pragma unroll
    for (int k = NB-1; k >= 0; k--){
        float2 ps = rot[w0 - k];
        float p = ps.x, s = ps.y;
        if ((u >> k) & 1){ p = -p; s = -s; }
        u64 pp = pk2(p, p), ss = pk2(s, s);
        const int bit = 1 << k;
        #pragma unroll
        for (int q = 0; q < (1 << NB); q++)
            if (!(q & bit)){
                u64 v0 = amp[q], v1 = amp[q | bit];
                u64 uu = f2(pp, v1, v0);       // u   = v0 + p*v1
                u64 w1 = f2(ss, uu, v1);       // v1' = v1 + s*u
                amp[q | bit] = w1;
                amp[q]       = f2(pp, w1, uu); // v0' = u + p*v1'
            }
    }
}

// ---------------- CNOT-ring permutation + smem swizzle (GF2 linear) ----------------
__host__ __device__ __forceinline__ constexpr int cpfwd(int i){
    int y = i;
    y ^= y >> 1; y ^= y >> 2; y ^= y >> 4; y ^= y >> 8;
    return (y & 0x1FFF) ^ ((((y ^ (i >> 13)) & 1) << 13));
}
__host__ __device__ __forceinline__ constexpr int cpinv(int o){
    int t = o ^ (o >> 1);
    return (t & 0x1FFF) ^ (o & 0x2000) ^ ((o & 1) ? 0x3000 : 0);
}
template<int L>
__host__ __device__ __forceinline__ constexpr int pinvL(int x){
    return (L == 0) ? x : (L == 1) ? cpinv(x) : cpinv(cpinv(x));
}
// linear bank swizzle: XOR bit 9 into bit 4 (fixes 4B-bank conflicts; self-composing)
__host__ __device__ __forceinline__ constexpr int sw(int a){
    return a ^ ((a >> 5) & 0x10);
}

// ---------------- passes ----------------

// pass A: logical bits 13..9 (wires 0..4), layer L>=1. Tiles tau = t + NT*it.
template<int L>
__device__ __forceinline__ void passA(u32* psi, const float2* stab, const float2* srot, int t){
    #pragma unroll 1
    for (int it = 0; it < 2; it++){
        int tau = t + NT*it;
        const float2* tab = stab + ((L == 1) ? OFF_A1 : OFF_A2)
                          + (((tau >> 4) & 31) << 6) + (tau & 1);
        int base = sw(pinvL<L>(tau));
        u64 amp[32];
        #pragma unroll
        for (int f = 0; f < 32; f++)
            amp[f] = ldamp(psi, base ^ sw(pinvL<L>(f << 9)), tab[f << 1]);
        rotTile<5>(amp, srot, L*NW + 4, 0);
        #pragma unroll
        for (int f = 0; f < 32; f++)
            stamp(psi, base ^ sw(pinvL<L>(f << 9)), amp[f]);
    }
}

// pass B: logical bits 8..4 (wires 5..9), layer L. Entry table idx (L<<9)|(f<<4)|q
// carries deltaB(L) + deltaC(L) (+ betaC(L-1)).
template<int L>
__device__ __forceinline__ void passB(u32* psi, const float2* stab, const float2* srot, int t){
    #pragma unroll 1
    for (int it = 0; it < 2; it++){
        int tau = t + NT*it;
        int q = tau & 15;
        int base = sw(pinvL<L>(((tau >> 4) << 9) | q));
        const float2* tab = stab + OFF_B0 + (L << 9) + q;
        u64 amp[32];
        #pragma unroll
        for (int f = 0; f < 32; f++)
            amp[f] = ldamp(psi, base ^ sw(pinvL<L>(f << 4)), tab[f << 4]);
        rotTile<5>(amp, srot, L*NW + 9, 0);
        #pragma unroll
        for (int f = 0; f < 32; f++)
            stamp(psi, base ^ sw(pinvL<L>(f << 4)), amp[f]);
    }
}

// stagger offset u for C passes; extra ^((t>>4)&1) differentiates half-warps (4B banks)
template<int L>
__device__ __forceinline__ int p3stagger(int t){
    int r4 = t & 15;
    int hw = (t >> 4) & 1;
    if (L == 0) return r4 ^ hw;
    if (L == 1){ int v = r4 ^ ((t & 1) << 3); return ((v ^ (v>>1) ^ (v>>2) ^ (v>>3)) & 15) ^ hw; }
    int v = r4 ^ ((t & 3) << 2); return ((v ^ (v >> 2)) & 15) ^ hw;
}

// pass C: logical bits 3..0 (wires 10..13), layer L. NO phase work (deltaC applied in B,
// betaC deferred / dropped). MEAS folds P^3 measurement with partial Walsh butterfly.
template<int L, bool MEAS>
__device__ __forceinline__ void passC(u32* psi, const float2* srot, int t, float* zs){
    const int u = p3stagger<L>(t);
    const int uoff = sw(pinvL<L>(u));
    #pragma unroll 1
    for (int tt = 0; tt < 4; tt++){
        int y = t + NT*tt;                        // 10-bit tile index (logical bits 13..4)
        int base = sw(pinvL<L>(y << 4)) ^ uoff;
        u64 amp[16];
        #pragma unroll
        for (int m = 0; m < 16; m++)
            amp[m] = ldraw(psi, base ^ sw(pinvL<L>(m)));
        rotTile<4>(amp, srot, L*NW + 13, u);
        if (!MEAS){
            #pragma unroll
            for (int m = 0; m < 16; m++)
                stamp(psi, base ^ sw(pinvL<L>(m)), amp[m]);
        } else {
            // logical o = cpfwd((y<<4) ^ u ^ m); cpfwd(m) sign bits live in o bits 3..0,13
            int obase = cpfwd((y << 4) ^ u);
            float pr[16];
            #pragma unroll
            for (int m = 0; m < 16; m++){
                float xx, yy; upk2(amp[m], xx, yy);
                pr[m] = xx*xx + yy*yy;
            }
            float P[8], Mv[8];
            #pragma unroll
            for (int j = 0; j < 8; j++){ P[j] = pr[2*j] + pr[2*j+1]; Mv[j] = pr[2*j] - pr[2*j+1]; }
            float Spar = Mv[0]-Mv[1]-Mv[2]+Mv[3]-Mv[4]+Mv[5]+Mv[6]-Mv[7];
            float PP[4], PM[4];
            #pragma unroll
            for (int k = 0; k < 4; k++){ PP[k] = P[2*k] + P[2*k+1]; PM[k] = P[2*k] - P[2*k+1]; }
            float S123 = PM[0]-PM[1]-PM[2]+PM[3];
            float PPP0 = PP[0]+PP[1], PPP1 = PP[2]+PP[3];
            float S23  = (PP[0]-PP[1]) - (PP[2]-PP[3]);
            float T    = PPP0 + PPP1;
            float S3   = PPP0 - PPP1;
            #pragma unroll
            for (int w = 1; w <= 9; w++){
                unsigned msk = ((unsigned)obase << (18 + w)) & 0x80000000u;
                zs[w] += __uint_as_float(__float_as_uint(T) ^ msk);
            }
            zs[0]  += __uint_as_float(__float_as_uint(Spar) ^ (((unsigned)obase << 18) & 0x80000000u));
            zs[13] += __uint_as_float(__float_as_uint(Spar) ^ (((unsigned)obase << 31) & 0x80000000u));
            zs[12] += __uint_as_float(__float_as_uint(S123) ^ (((unsigned)obase << 30) & 0x80000000u));
            zs[11] += __uint_as_float(__float_as_uint(S23)  ^ (((unsigned)obase << 29) & 0x80000000u));
            zs[10] += __uint_as_float(__float_as_uint(S3)   ^ (((unsigned)obase << 28) & 0x80000000u));
        }
    }
}

// ---------------- main kernel ----------------

__global__ void __launch_bounds__(NT, 2)
qsim_kernel(const float* __restrict__ sr, const float* __restrict__ si,
            const float* __restrict__ hw, const float* __restrict__ hb,
            float* __restrict__ out)
{
    extern __shared__ u32 smu[];
    u32* psi = smu;                                           // half2 per amp
    float2* stab = reinterpret_cast<float2*>(smu + DIM);      // NTAB float2
    float2* srot = stab + NTAB;                               // 42 float2
    const int t = threadIdx.x;
    const int b = blockIdx.x;

    #pragma unroll 1
    for (int i = t; i < NTAB; i += NT) stab[i] = g_tab[i];
    if (t < 3*NW) srot[t] = g_rot[t];
    __syncthreads();

    // ---- layer 0 pass A fused with global load ----
    {
        const float* srb = sr + (size_t)b * DIM;
        const float* sib = si + (size_t)b * DIM;
        const float2* tab = stab + OFF_A0;
        #pragma unroll 1
        for (int it = 0; it < 2; it++){
            int tau = t + NT*it;
            u64 amp[32];
            #pragma unroll
            for (int f = 0; f < 32; f++){
                float re = __ldg(srb + (f << 9) + tau);
                float im = __ldg(sib + (f << 9) + tau);
                float2 q = tab[f];
                float xr = fmaf(q.x, re, -q.y * im);
                float yi = fmaf(q.x, im,  q.y * re);
                amp[f] = pk2(xr, yi);
            }
            rotTile<5>(amp, srot, 4, 0);
            #pragma unroll
            for (int f = 0; f < 32; f++)
                stamp(psi, tau ^ sw(f << 9), amp[f]);
        }
    }
    __syncthreads();
    passB<0>(psi, stab, srot, t);       __syncthreads();
    passC<0,false>(psi, srot, t, 0);    __syncthreads();

    passA<1>(psi, stab, srot, t);       __syncthreads();
    passB<1>(psi, stab, srot, t);       __syncthreads();
    passC<1,false>(psi, srot, t, 0);    __syncthreads();

    passA<2>(psi, stab, srot, t);       __syncthreads();
    passB<2>(psi, stab, srot, t);       __syncthreads();

    // ---- layer 2 pass C + measurement (P^3 folded; all exit diagonals dropped) ----
    float zs[NW];
    #pragma unroll
    for (int w = 0; w < NW; w++) zs[w] = 0.f;
    passC<2,true>(psi, srot, t, zs);

    // warp reduce
    #pragma unroll
    for (int off = 16; off > 0; off >>= 1)
        #pragma unroll
        for (int w = 0; w < NW; w++)
            zs[w] += __shfl_down_sync(0xffffffffu, zs[w], off);
    __syncthreads();                       // all psi reads done; reuse as scratch
    float* red = reinterpret_cast<float*>(psi);
    const int NWARP = NT/32;
    int lane = t & 31, wid = t >> 5;
    if (lane == 0){
        #pragma unroll
        for (int w = 0; w < NW; w++) red[w*NWARP + wid] = zs[w];
    }
    __syncthreads();
    if (t == 0){
        float acc = __ldg(hb);
        #pragma unroll
        for (int w = 0; w < NW; w++){
            float f = 0.f;
            #pragma unroll
            for (int r = 0; r < NWARP; r++) f += red[w*NWARP + r];
            acc += f * __ldg(hw + w);
        }
        out[b] = acc;
    }
}

// ---------------- launch ----------------

extern "C" void kernel_launch(void* const* d_in, const int* in_sizes, int n_in,
                              void* d_out, int out_size)
{
    const float* sr = (const float*)d_in[0];
    const float* si = (const float*)d_in[1];
    const float* vp = (const float*)d_in[2];
    const float* hw = (const float*)d_in[3];
    const float* hb = (const float*)d_in[4];
    float* out = (float*)d_out;

    const int SMEM = DIM*sizeof(u32) + NTAB*sizeof(float2) + 3*NW*sizeof(float2);

    cudaFuncSetAttribute(qsim_kernel, cudaFuncAttributeMaxDynamicSharedMemorySize, SMEM);

    setup_all<<<1, 1024>>>(vp);

    int B = in_sizes[0] / DIM;
    qsim_kernel<<<B, NT, SMEM>>>(sr, si, hw, hb, out);
}